// round 3
// baseline (speedup 1.0000x reference)
#include <cuda_runtime.h>
#include <math.h>

// XConv fused kernel for GB300 (sm_103a), round 2: 512 threads/CTA, overlap weight staging.
// Shapes: N=16,P=1024,K=16,DIMS=3,C_IN=64,C_MID=64,C_CAT=128,KK=256,DM=4,C_OUT=128

namespace {

constexpr int KNB   = 16;
constexpr int G     = 8;     // points per CTA
constexpr int T     = 512;   // threads per CTA
constexpr int CCAT  = 128;

// shared memory layout (float offsets)
constexpr int OFF_W1  = 0;        // 192
constexpr int OFF_B1  = 192;      // 64
constexpr int OFF_B2  = 256;      // 64
constexpr int OFF_PLT = 320;      // 384   plT[g][d][k]
constexpr int OFF_FC  = 704;      // 16384 fts_cat[g*16+k][128]
constexpr int OFF_WS  = 17088;    // 8448  (union: w2 4096 / wdwT 64*132=8448)
constexpr int OFF_WC1 = 25536;    // 12544 wc1 pitched 256*49
constexpr int OFF_R   = 38080;    // 8448  (union: h1 128*66 / X0T 2048+X1T 2048 / X0T+dw 4096)
constexpr int SMEM_FLOATS = 46528;  // 186112 bytes

__device__ __forceinline__ float elu1(float x) { return x > 0.f ? x : expm1f(x); }

__global__ void __launch_bounds__(T, 1)
xconv_kernel(const float* __restrict__ rep_pt, const float* __restrict__ pts,
             const float* __restrict__ fts,
             const float* __restrict__ w1,  const float* __restrict__ b1,
             const float* __restrict__ w2,  const float* __restrict__ b2,
             const float* __restrict__ wc1, const float* __restrict__ bc1,
             const float* __restrict__ wx1, const float* __restrict__ bx1,
             const float* __restrict__ wx2, const float* __restrict__ bx2,
             const float* __restrict__ wdw, const float* __restrict__ bdw,
             const float* __restrict__ wpw, const float* __restrict__ bpw,
             const float* __restrict__ bng, const float* __restrict__ bnb,
             const float* __restrict__ bnm, const float* __restrict__ bnv,
             float* __restrict__ out)
{
    extern __shared__ float sm[];
    float* w1s  = sm + OFF_W1;
    float* b1s  = sm + OFF_B1;
    float* b2s  = sm + OFF_B2;
    float* plT  = sm + OFF_PLT;   // [g][d][k] : g*48 + d*16 + k
    float* fc   = sm + OFF_FC;    // [g*16+k][128]
    float* ws   = sm + OFF_WS;    // w2, later wdwT (pitch 132)
    float* wc1s = sm + OFF_WC1;   // wc1 pitched 49
    float* R    = sm + OFF_R;

    const int t = threadIdx.x;
    const int pbase = blockIdx.x * G;

    // ---- Stage A0: stage all early weights + inputs ----
    for (int i = t; i < 192; i += T) w1s[i] = w1[i];
    if (t < 64) { b1s[t] = b1[t]; b2s[t] = b2[t]; }
    for (int i = t; i < 4096; i += T) ws[i] = w2[i];
    // wc1 (o, m=d*16+k) -> pitched 49 (conflict-free column reads)
    for (int i = t; i < 256 * 48; i += T) {
        int o = i / 48, m = i - o * 48;
        wc1s[o * 49 + m] = wc1[i];
    }
    // pts_local transposed: plT[g][d][k]
    for (int i = t; i < G * 48; i += T) {
        int g = i / 48, r = i - g * 48, d = r >> 4, k = r & 15;
        int pp = pbase + g;
        plT[i] = pts[(pp * KNB + k) * 3 + d] - rep_pt[pp * 3 + d];
    }
    // fts into fts_cat columns 64..127 (coalesced)
    for (int i = t; i < G * KNB * 64; i += T) {
        int g = i >> 10, rem = i & 1023, k = rem >> 6, c = rem & 63;
        fc[(g * KNB + k) * CCAT + 64 + c] = fts[(size_t)(pbase + g) * 1024 + rem];
    }
    __syncthreads();

    // ---- Stage A1: h1 = elu(pl @ w1 + b1)  (128 rows x 64 cols, pitch 66) ----
    float* h1 = R;
    {
        int row = t >> 2, g = row >> 4, k = row & 15, cb = (t & 3) * 16;
        float p0 = plT[g * 48 + k];
        float p1 = plT[g * 48 + 16 + k];
        float p2 = plT[g * 48 + 32 + k];
        #pragma unroll
        for (int c = 0; c < 16; c++) {
            float a = b1s[cb + c] + p0 * w1s[cb + c] + p1 * w1s[64 + cb + c]
                      + p2 * w1s[128 + cb + c];
            h1[row * 66 + cb + c] = elu1(a);
        }
    }
    __syncthreads();

    // ---- Stage A2: h2 = elu(h1 @ w2 + b2) -> fc[:, 0:64] ----
    {
        int tc = t & 15, tr = t >> 4;          // 16 col-groups x 32 row-groups
        float acc[4][4];
        #pragma unroll
        for (int i = 0; i < 4; i++)
            #pragma unroll
            for (int c = 0; c < 4; c++) acc[i][c] = b2s[tc * 4 + c];
        #pragma unroll 8
        for (int j = 0; j < 64; j++) {
            float4 w = *(const float4*)&ws[j * 64 + tc * 4];
            #pragma unroll
            for (int i = 0; i < 4; i++) {
                float hv = h1[(tr * 4 + i) * 66 + j];
                acc[i][0] += hv * w.x; acc[i][1] += hv * w.y;
                acc[i][2] += hv * w.z; acc[i][3] += hv * w.w;
            }
        }
        #pragma unroll
        for (int i = 0; i < 4; i++) {
            int row = tr * 4 + i;
            float4 o = {elu1(acc[i][0]), elu1(acc[i][1]), elu1(acc[i][2]), elu1(acc[i][3])};
            *(float4*)&fc[row * CCAT + tc * 4] = o;
        }
    }
    __syncthreads();

    // ---- wdwT staging (w2 region dead): issue now, drains under B/C ----
    for (int i = t; i < 8192; i += T) {
        int c = i >> 6, r = i & 63;            // r = d*16 + k
        ws[r * 132 + c] = wdw[i];
    }
    // (no sync: consumed after the C2 barrier)

    // ---- Stage B: X0 = elu(pl_flat @ wc1^T + bc1), transposed X0T[o][g] ----
    float* X0T = R;            // 256*8
    float* X1T = R + 2048;     // 256*8
    {
        int g = t >> 6, lane = t & 63;
        float acc[4];
        #pragma unroll
        for (int q = 0; q < 4; q++) acc[q] = bc1[lane + 64 * q];
        const float* pg = plT + g * 48;
        #pragma unroll 8
        for (int m = 0; m < 48; m++) {
            float pv = pg[m];
            #pragma unroll
            for (int q = 0; q < 4; q++) acc[q] += pv * wc1s[(lane + 64 * q) * 49 + m];
        }
        #pragma unroll
        for (int q = 0; q < 4; q++) X0T[(lane + 64 * q) * 8 + g] = elu1(acc[q]);
    }
    __syncthreads();

    // ---- Stage C1: X1 = elu(X0 @ wx1 + bx1) ----
    {
        int c = (t & 127) * 2;    // column pair
        int gq = t >> 7;          // g pair index 0..3
        float2 bb = *(const float2*)&bx1[c];
        float a00 = bb.x, a01 = bb.y, a10 = bb.x, a11 = bb.y;  // a[gi][ci]
        #pragma unroll 8
        for (int j = 0; j < 256; j++) {
            float2 w = *(const float2*)&wx1[j * 256 + c];
            float2 x = *(const float2*)&X0T[j * 8 + gq * 2];
            a00 += x.x * w.x; a01 += x.x * w.y;
            a10 += x.y * w.x; a11 += x.y * w.y;
        }
        float2 s0 = {elu1(a00), elu1(a10)};
        float2 s1 = {elu1(a01), elu1(a11)};
        *(float2*)&X1T[c * 8 + gq * 2]       = s0;
        *(float2*)&X1T[(c + 1) * 8 + gq * 2] = s1;
    }
    __syncthreads();

    // ---- Stage C2: Xf = X1 @ wx2 + bx2 (no activation) -> X0T ----
    {
        int c = (t & 127) * 2;
        int gq = t >> 7;
        float2 bb = *(const float2*)&bx2[c];
        float a00 = bb.x, a01 = bb.y, a10 = bb.x, a11 = bb.y;
        #pragma unroll 8
        for (int j = 0; j < 256; j++) {
            float2 w = *(const float2*)&wx2[j * 256 + c];
            float2 x = *(const float2*)&X1T[j * 8 + gq * 2];
            a00 += x.x * w.x; a01 += x.x * w.y;
            a10 += x.y * w.x; a11 += x.y * w.y;
        }
        float2 s0 = {a00, a10};
        float2 s1 = {a01, a11};
        *(float2*)&X0T[c * 8 + gq * 2]       = s0;
        *(float2*)&X0T[(c + 1) * 8 + gq * 2] = s1;
    }
    __syncthreads();   // also publishes wdwT

    // ---- Stage D: fts_X = X @ fts_cat, then depthwise -> dw[g][512] ----
    float* dws = R + 2048;   // X1T dead; Xf (X0T) stays live in R[0..2047]
    {
        int g = t >> 6, lane = t & 63;
        int c0 = lane * 2;
        float dwacc[2][4];
        #pragma unroll
        for (int cc = 0; cc < 2; cc++) {
            float4 bb = *(const float4*)&bdw[(c0 + cc) * 4];
            dwacc[cc][0] = bb.x; dwacc[cc][1] = bb.y;
            dwacc[cc][2] = bb.z; dwacc[cc][3] = bb.w;
        }
        #pragma unroll
        for (int i = 0; i < 16; i++) {
            float fx0 = 0.f, fx1 = 0.f;
            #pragma unroll
            for (int j = 0; j < 16; j++) {
                float xv = X0T[(i * 16 + j) * 8 + g];                 // broadcast
                float2 f = *(const float2*)&fc[(g * 16 + j) * CCAT + c0];
                fx0 += xv * f.x; fx1 += xv * f.y;
            }
            #pragma unroll
            for (int d = 0; d < 4; d++) {
                float2 wd = *(const float2*)&ws[(d * 16 + i) * 132 + c0];
                dwacc[0][d] += fx0 * wd.x;
                dwacc[1][d] += fx1 * wd.y;
            }
        }
        #pragma unroll
        for (int cc = 0; cc < 2; cc++) {
            float4 v = {dwacc[cc][0], dwacc[cc][1], dwacc[cc][2], dwacc[cc][3]};
            *(float4*)&dws[g * 512 + (c0 + cc) * 4] = v;   // m = c*4 + d
        }
    }
    __syncthreads();

    // ---- Stage E: y = BN(elu(dw @ wpw + bpw)) ----
    {
        int o = (t & 63) * 2;
        int g = t >> 6;
        float2 bb = *(const float2*)&bpw[o];
        float a0 = bb.x, a1 = bb.y;
        const float* dg = dws + g * 512;
        #pragma unroll 8
        for (int m = 0; m < 512; m++) {
            float2 w = *(const float2*)&wpw[m * 128 + o];
            float dv = dg[m];                                   // broadcast
            a0 += dv * w.x; a1 += dv * w.y;
        }
        float2 gv = *(const float2*)&bng[o];
        float2 vv = *(const float2*)&bnv[o];
        float2 mv = *(const float2*)&bnm[o];
        float2 ev = *(const float2*)&bnb[o];
        float s0 = gv.x * rsqrtf(vv.x + 1e-5f);
        float s1 = gv.y * rsqrtf(vv.y + 1e-5f);
        float2 y = {(elu1(a0) - mv.x) * s0 + ev.x,
                    (elu1(a1) - mv.y) * s1 + ev.y};
        *(float2*)&out[(size_t)(pbase + g) * 128 + o] = y;
    }
}

} // namespace

extern "C" void kernel_launch(void* const* d_in, const int* in_sizes, int n_in,
                              void* d_out, int out_size) {
    const float* rep_pt = (const float*)d_in[0];
    const float* pts    = (const float*)d_in[1];
    const float* fts    = (const float*)d_in[2];
    const float* w1     = (const float*)d_in[3];
    const float* b1     = (const float*)d_in[4];
    const float* w2     = (const float*)d_in[5];
    const float* b2     = (const float*)d_in[6];
    const float* wc1    = (const float*)d_in[7];
    const float* bc1    = (const float*)d_in[8];
    const float* wx1    = (const float*)d_in[9];
    const float* bx1    = (const float*)d_in[10];
    const float* wx2    = (const float*)d_in[11];
    const float* bx2    = (const float*)d_in[12];
    const float* wdw    = (const float*)d_in[13];
    const float* bdw    = (const float*)d_in[14];
    const float* wpw    = (const float*)d_in[15];
    const float* bpw    = (const float*)d_in[16];
    const float* bng    = (const float*)d_in[17];
    const float* bnb    = (const float*)d_in[18];
    const float* bnm    = (const float*)d_in[19];
    const float* bnv    = (const float*)d_in[20];
    float* out = (float*)d_out;

    const size_t smem_bytes = (size_t)SMEM_FLOATS * sizeof(float);
    cudaFuncSetAttribute(xconv_kernel,
                         cudaFuncAttributeMaxDynamicSharedMemorySize,
                         (int)smem_bytes);

    const int n_points = 16 * 1024;
    const int grid = n_points / G;   // 2048 CTAs
    xconv_kernel<<<grid, T, smem_bytes>>>(
        rep_pt, pts, fts, w1, b1, w2, b2, wc1, bc1,
        wx1, bx1, wx2, bx2, wdw, bdw, wpw, bpw,
        bng, bnb, bnm, bnv, out);
}

// round 4
// speedup vs baseline: 1.4015x; 1.4015x over previous
#include <cuda_runtime.h>
#include <math.h>

namespace {

constexpr int NPTS = 16384;   // N * P

// global scratch (allowed: __device__ arrays)
__device__ float g_h2[NPTS * 1024];   // [pt][k(16)][64] lifted features
__device__ float g_X0[NPTS * 256];    // [pt][256]
__device__ float g_X1[NPTS * 256];
__device__ float g_Xf[NPTS * 256];
__device__ float g_dw[NPTS * 512];    // [pt][m=c*4+d]

__device__ __forceinline__ float elu1(float x) { return x > 0.f ? x : expm1f(x); }

// ============================ Kernel A ============================
// per 16 points: pts_local, h1=elu(pl@w1+b1), h2=elu(h1@w2+b2)->g_h2, X0->g_X0
constexpr int A_T = 512;
constexpr int A_W1  = 0;       // 192
constexpr int A_B1  = 192;     // 64
constexpr int A_B2  = 256;     // 64
constexpr int A_PLT = 320;     // 768  plT[g(16)][d(3)][k(16)]
constexpr int A_W2  = 1088;    // 4096
constexpr int A_WC1 = 5184;    // 12544 (256 x pitch49)
constexpr int A_H1  = 17728;   // 16896 (256 rows x pitch 66)
constexpr int A_SMEM = 34624;  // floats (138.5 KB)

__global__ void __launch_bounds__(A_T, 1)
kernelA(const float* __restrict__ rep_pt, const float* __restrict__ pts,
        const float* __restrict__ w1,  const float* __restrict__ b1,
        const float* __restrict__ w2,  const float* __restrict__ b2,
        const float* __restrict__ wc1, const float* __restrict__ bc1)
{
    extern __shared__ float sm[];
    float* w1s  = sm + A_W1;
    float* b1s  = sm + A_B1;
    float* b2s  = sm + A_B2;
    float* plT  = sm + A_PLT;
    float* w2s  = sm + A_W2;
    float* wc1s = sm + A_WC1;
    float* h1   = sm + A_H1;

    const int t = threadIdx.x;
    const int pbase = blockIdx.x * 16;

    // stage weights + inputs
    for (int i = t; i < 192; i += A_T) w1s[i] = w1[i];
    if (t < 64) { b1s[t] = b1[t]; b2s[t] = b2[t]; }
    for (int i = t; i < 4096; i += A_T) w2s[i] = w2[i];
    for (int i = t; i < 256 * 48; i += A_T) {
        int o = i / 48, m = i - o * 48;
        wc1s[o * 49 + m] = wc1[i];
    }
    for (int i = t; i < 768; i += A_T) {
        int g = i / 48, r = i - g * 48, d = r >> 4, k = r & 15;
        int pp = pbase + g;
        plT[i] = pts[(pp * 16 + k) * 3 + d] - rep_pt[pp * 3 + d];
    }
    __syncthreads();

    // A1: h1 (256 rows x 64, pitch 66)
    {
        int row = t >> 1, g = row >> 4, k = row & 15, cb = (t & 1) * 32;
        float p0 = plT[g * 48 + k];
        float p1 = plT[g * 48 + 16 + k];
        float p2 = plT[g * 48 + 32 + k];
        #pragma unroll
        for (int c = 0; c < 32; c++) {
            float a = b1s[cb + c] + p0 * w1s[cb + c] + p1 * w1s[64 + cb + c]
                      + p2 * w1s[128 + cb + c];
            h1[row * 66 + cb + c] = elu1(a);
        }
    }
    __syncthreads();

    // A2: h2 = elu(h1 @ w2 + b2) -> g_h2 (rows 256 x cols 64)
    {
        int tc = t & 15, tr = t >> 4;    // cols tc*4, rows tr*8..
        float acc[8][4];
        #pragma unroll
        for (int i = 0; i < 8; i++)
            #pragma unroll
            for (int c = 0; c < 4; c++) acc[i][c] = b2s[tc * 4 + c];
        #pragma unroll 8
        for (int j = 0; j < 64; j++) {
            float4 w = *(const float4*)&w2s[j * 64 + tc * 4];
            #pragma unroll
            for (int i = 0; i < 8; i++) {
                float hv = h1[(tr * 8 + i) * 66 + j];
                acc[i][0] += hv * w.x; acc[i][1] += hv * w.y;
                acc[i][2] += hv * w.z; acc[i][3] += hv * w.w;
            }
        }
        #pragma unroll
        for (int i = 0; i < 8; i++) {
            int r = tr * 8 + i;
            float4 o = {elu1(acc[i][0]), elu1(acc[i][1]), elu1(acc[i][2]), elu1(acc[i][3])};
            *(float4*)&g_h2[(size_t)pbase * 1024 + r * 64 + tc * 4] = o;
        }
    }

    // B: X0 = elu(pl_flat @ wc1^T + bc1) -> g_X0 [pt][256]
    {
        int g = t >> 5, lane = t & 31;
        float acc[8];
        #pragma unroll
        for (int q = 0; q < 8; q++) acc[q] = bc1[lane + 32 * q];
        const float* pg = plT + g * 48;
        #pragma unroll 8
        for (int m = 0; m < 48; m++) {
            float pv = pg[m];
            #pragma unroll
            for (int q = 0; q < 8; q++) acc[q] += pv * wc1s[(lane + 32 * q) * 49 + m];
        }
        #pragma unroll
        for (int q = 0; q < 8; q++)
            g_X0[(size_t)(pbase + g) * 256 + lane + 32 * q] = elu1(acc[q]);
    }
}

// ============================ GEMM 16384x256x256 ============================
// C = act(A @ W + bias); tile 128Mx128N, K-steps of 16, micro 8x8, 256 thr.
template <int ACT>
__global__ void __launch_bounds__(256, 2)
gemm256(const float* __restrict__ A, const float* __restrict__ W,
        const float* __restrict__ bias, float* __restrict__ C)
{
    __shared__ float As[2][16][132];
    __shared__ float Ws[2][16][128];
    const int tid = threadIdx.x;
    const int bm = blockIdx.x >> 1, bn = blockIdx.x & 1;
    const int tm = tid >> 4, tn = tid & 15;
    const float* Ab = A + (size_t)bm * 128 * 256;
    const float* Wb = W + bn * 128;

    const int f0 = tid, f1 = tid + 256;
    const int ar0 = f0 >> 2, ac0 = (f0 & 3) * 4;
    const int ar1 = f1 >> 2, ac1 = (f1 & 3) * 4;
    const int wr0 = f0 >> 5, wc0 = (f0 & 31) * 4;
    const int wr1 = f1 >> 5, wc1_ = (f1 & 31) * 4;

    float acc[8][8];
    #pragma unroll
    for (int i = 0; i < 8; i++)
        #pragma unroll
        for (int j = 0; j < 8; j++) acc[i][j] = 0.f;

    float4 ra0, ra1, rw0, rw1;

    // tile 0 -> smem buf 0
    ra0 = *(const float4*)&Ab[ar0 * 256 + ac0];
    ra1 = *(const float4*)&Ab[ar1 * 256 + ac1];
    rw0 = *(const float4*)&Wb[wr0 * 256 + wc0];
    rw1 = *(const float4*)&Wb[wr1 * 256 + wc1_];
    As[0][ac0 + 0][ar0] = ra0.x; As[0][ac0 + 1][ar0] = ra0.y;
    As[0][ac0 + 2][ar0] = ra0.z; As[0][ac0 + 3][ar0] = ra0.w;
    As[0][ac1 + 0][ar1] = ra1.x; As[0][ac1 + 1][ar1] = ra1.y;
    As[0][ac1 + 2][ar1] = ra1.z; As[0][ac1 + 3][ar1] = ra1.w;
    *(float4*)&Ws[0][wr0][wc0]  = rw0;
    *(float4*)&Ws[0][wr1][wc1_] = rw1;
    __syncthreads();

    // prefetch tile 1 into regs
    ra0 = *(const float4*)&Ab[ar0 * 256 + 16 + ac0];
    ra1 = *(const float4*)&Ab[ar1 * 256 + 16 + ac1];
    rw0 = *(const float4*)&Wb[(16 + wr0) * 256 + wc0];
    rw1 = *(const float4*)&Wb[(16 + wr1) * 256 + wc1_];

    for (int kt = 0; kt < 16; kt++) {
        const int cur = kt & 1;
        if (kt < 15) {   // commit regs (tile kt+1) into other buffer
            As[cur ^ 1][ac0 + 0][ar0] = ra0.x; As[cur ^ 1][ac0 + 1][ar0] = ra0.y;
            As[cur ^ 1][ac0 + 2][ar0] = ra0.z; As[cur ^ 1][ac0 + 3][ar0] = ra0.w;
            As[cur ^ 1][ac1 + 0][ar1] = ra1.x; As[cur ^ 1][ac1 + 1][ar1] = ra1.y;
            As[cur ^ 1][ac1 + 2][ar1] = ra1.z; As[cur ^ 1][ac1 + 3][ar1] = ra1.w;
            *(float4*)&Ws[cur ^ 1][wr0][wc0]  = rw0;
            *(float4*)&Ws[cur ^ 1][wr1][wc1_] = rw1;
        }
        if (kt < 14) {   // prefetch tile kt+2
            const int k0 = (kt + 2) * 16;
            ra0 = *(const float4*)&Ab[ar0 * 256 + k0 + ac0];
            ra1 = *(const float4*)&Ab[ar1 * 256 + k0 + ac1];
            rw0 = *(const float4*)&Wb[(k0 + wr0) * 256 + wc0];
            rw1 = *(const float4*)&Wb[(k0 + wr1) * 256 + wc1_];
        }
        #pragma unroll
        for (int kk = 0; kk < 16; kk++) {
            float4 a0 = *(const float4*)&As[cur][kk][tm * 8];
            float4 a1 = *(const float4*)&As[cur][kk][tm * 8 + 4];
            float4 b0 = *(const float4*)&Ws[cur][kk][tn * 8];
            float4 b1 = *(const float4*)&Ws[cur][kk][tn * 8 + 4];
            float av[8] = {a0.x, a0.y, a0.z, a0.w, a1.x, a1.y, a1.z, a1.w};
            float bv[8] = {b0.x, b0.y, b0.z, b0.w, b1.x, b1.y, b1.z, b1.w};
            #pragma unroll
            for (int i = 0; i < 8; i++)
                #pragma unroll
                for (int j = 0; j < 8; j++) acc[i][j] += av[i] * bv[j];
        }
        __syncthreads();
    }

    // epilogue
    const int row0 = bm * 128 + tm * 8;
    const int col0 = bn * 128 + tn * 8;
    float4 bs0 = *(const float4*)&bias[col0];
    float4 bs1 = *(const float4*)&bias[col0 + 4];
    float bb[8] = {bs0.x, bs0.y, bs0.z, bs0.w, bs1.x, bs1.y, bs1.z, bs1.w};
    #pragma unroll
    for (int i = 0; i < 8; i++) {
        float v[8];
        #pragma unroll
        for (int j = 0; j < 8; j++) {
            float x = acc[i][j] + bb[j];
            v[j] = ACT ? elu1(x) : x;
        }
        float4 o0 = {v[0], v[1], v[2], v[3]};
        float4 o1 = {v[4], v[5], v[6], v[7]};
        *(float4*)&C[(size_t)(row0 + i) * 256 + col0]     = o0;
        *(float4*)&C[(size_t)(row0 + i) * 256 + col0 + 4] = o1;
    }
}

// ============================ Kernel D ============================
// per 16 points: fts_X = Xf(16x16) @ [h2|fts](16x128); depthwise -> g_dw
constexpr int D_T = 512;
constexpr int D_FC  = 0;        // 32768 fc[256][128]
constexpr int D_XF  = 32768;    // 4096  Xfs[16][256]
constexpr int D_WDW = 36864;    // 8448  wdwT (64 x pitch132)
constexpr int D_SMEM = 45312;   // floats (181.2 KB)

__global__ void __launch_bounds__(D_T, 1)
kernelD(const float* __restrict__ fts, const float* __restrict__ wdw,
        const float* __restrict__ bdw)
{
    extern __shared__ float sm[];
    float* fcs  = sm + D_FC;
    float* Xfs  = sm + D_XF;
    float* wdwT = sm + D_WDW;

    const int t = threadIdx.x;
    const int pbase = blockIdx.x * 16;

    for (int i = t; i < 16384; i += D_T)
        fcs[(i >> 6) * 128 + (i & 63)] = g_h2[(size_t)pbase * 1024 + i];
    for (int i = t; i < 16384; i += D_T)
        fcs[(i >> 6) * 128 + 64 + (i & 63)] = fts[(size_t)pbase * 1024 + i];
    for (int i = t; i < 4096; i += D_T)
        Xfs[i] = g_Xf[(size_t)pbase * 256 + i];
    for (int i = t; i < 8192; i += D_T) {
        int c = i >> 6, r = i & 63;           // r = d*16 + k
        wdwT[r * 132 + c] = wdw[i];
    }
    __syncthreads();

    const int g = t >> 5, lane = t & 31, c0 = lane * 4;

    float4 fr[16];
    #pragma unroll
    for (int j = 0; j < 16; j++)
        fr[j] = *(const float4*)&fcs[(g * 16 + j) * 128 + c0];

    float d0[4], d1[4], d2[4], d3[4];   // dwacc[channel cc][d]
    {
        float4 b0 = *(const float4*)&bdw[(c0 + 0) * 4];
        float4 b1 = *(const float4*)&bdw[(c0 + 1) * 4];
        float4 b2 = *(const float4*)&bdw[(c0 + 2) * 4];
        float4 b3 = *(const float4*)&bdw[(c0 + 3) * 4];
        d0[0]=b0.x; d0[1]=b0.y; d0[2]=b0.z; d0[3]=b0.w;
        d1[0]=b1.x; d1[1]=b1.y; d1[2]=b1.z; d1[3]=b1.w;
        d2[0]=b2.x; d2[1]=b2.y; d2[2]=b2.z; d2[3]=b2.w;
        d3[0]=b3.x; d3[1]=b3.y; d3[2]=b3.z; d3[3]=b3.w;
    }

    #pragma unroll
    for (int i = 0; i < 16; i++) {
        float fx0 = 0.f, fx1 = 0.f, fx2 = 0.f, fx3 = 0.f;
        #pragma unroll
        for (int j = 0; j < 16; j++) {
            float xv = Xfs[g * 256 + i * 16 + j];   // warp broadcast
            fx0 += xv * fr[j].x; fx1 += xv * fr[j].y;
            fx2 += xv * fr[j].z; fx3 += xv * fr[j].w;
        }
        #pragma unroll
        for (int d = 0; d < 4; d++) {
            float4 wd = *(const float4*)&wdwT[(d * 16 + i) * 132 + c0];
            d0[d] += fx0 * wd.x;
            d1[d] += fx1 * wd.y;
            d2[d] += fx2 * wd.z;
            d3[d] += fx3 * wd.w;
        }
    }

    float* dst = &g_dw[(size_t)(pbase + g) * 512 + c0 * 4];
    *(float4*)&dst[0]  = make_float4(d0[0], d0[1], d0[2], d0[3]);
    *(float4*)&dst[4]  = make_float4(d1[0], d1[1], d1[2], d1[3]);
    *(float4*)&dst[8]  = make_float4(d2[0], d2[1], d2[2], d2[3]);
    *(float4*)&dst[12] = make_float4(d3[0], d3[1], d3[2], d3[3]);
}

// ============================ GEMM E: 16384x128x512 + BN ============================
// out = BN(elu(dw @ wpw + bpw)); tile 64Mx128N, K-steps 16x32, micro 4x8, 256 thr.
__global__ void __launch_bounds__(256, 2)
gemm_out(const float* __restrict__ wpw, const float* __restrict__ bpw,
         const float* __restrict__ bng, const float* __restrict__ bnb,
         const float* __restrict__ bnm, const float* __restrict__ bnv,
         float* __restrict__ out)
{
    __shared__ float As[2][16][68];
    __shared__ float Ws[2][16][128];
    const int tid = threadIdx.x;
    const int bm = blockIdx.x;
    const int tm = tid >> 4, tn = tid & 15;
    const float* Ab = g_dw + (size_t)bm * 64 * 512;

    const int ar = tid >> 2, ac = (tid & 3) * 4;
    const int f0 = tid, f1 = tid + 256;
    const int wr0 = f0 >> 5, wc0 = (f0 & 31) * 4;
    const int wr1 = f1 >> 5, wc1_ = (f1 & 31) * 4;

    float acc[4][8];
    #pragma unroll
    for (int i = 0; i < 4; i++)
        #pragma unroll
        for (int j = 0; j < 8; j++) acc[i][j] = 0.f;

    float4 ra, rw0, rw1;
    ra  = *(const float4*)&Ab[ar * 512 + ac];
    rw0 = *(const float4*)&wpw[wr0 * 128 + wc0];
    rw1 = *(const float4*)&wpw[wr1 * 128 + wc1_];
    As[0][ac + 0][ar] = ra.x; As[0][ac + 1][ar] = ra.y;
    As[0][ac + 2][ar] = ra.z; As[0][ac + 3][ar] = ra.w;
    *(float4*)&Ws[0][wr0][wc0]  = rw0;
    *(float4*)&Ws[0][wr1][wc1_] = rw1;
    __syncthreads();

    ra  = *(const float4*)&Ab[ar * 512 + 16 + ac];
    rw0 = *(const float4*)&wpw[(16 + wr0) * 128 + wc0];
    rw1 = *(const float4*)&wpw[(16 + wr1) * 128 + wc1_];

    for (int kt = 0; kt < 32; kt++) {
        const int cur = kt & 1;
        if (kt < 31) {
            As[cur ^ 1][ac + 0][ar] = ra.x; As[cur ^ 1][ac + 1][ar] = ra.y;
            As[cur ^ 1][ac + 2][ar] = ra.z; As[cur ^ 1][ac + 3][ar] = ra.w;
            *(float4*)&Ws[cur ^ 1][wr0][wc0]  = rw0;
            *(float4*)&Ws[cur ^ 1][wr1][wc1_] = rw1;
        }
        if (kt < 30) {
            const int k0 = (kt + 2) * 16;
            ra  = *(const float4*)&Ab[ar * 512 + k0 + ac];
            rw0 = *(const float4*)&wpw[(k0 + wr0) * 128 + wc0];
            rw1 = *(const float4*)&wpw[(k0 + wr1) * 128 + wc1_];
        }
        #pragma unroll
        for (int kk = 0; kk < 16; kk++) {
            float4 a = *(const float4*)&As[cur][kk][tm * 4];
            float4 b0 = *(const float4*)&Ws[cur][kk][tn * 8];
            float4 b1 = *(const float4*)&Ws[cur][kk][tn * 8 + 4];
            float av[4] = {a.x, a.y, a.z, a.w};
            float bv[8] = {b0.x, b0.y, b0.z, b0.w, b1.x, b1.y, b1.z, b1.w};
            #pragma unroll
            for (int i = 0; i < 4; i++)
                #pragma unroll
                for (int j = 0; j < 8; j++) acc[i][j] += av[i] * bv[j];
        }
        __syncthreads();
    }

    // epilogue: bias + ELU + BN
    const int col0 = tn * 8;
    float4 bp0 = *(const float4*)&bpw[col0], bp1 = *(const float4*)&bpw[col0 + 4];
    float4 gm0 = *(const float4*)&bng[col0], gm1 = *(const float4*)&bng[col0 + 4];
    float4 vr0 = *(const float4*)&bnv[col0], vr1 = *(const float4*)&bnv[col0 + 4];
    float4 mn0 = *(const float4*)&bnm[col0], mn1 = *(const float4*)&bnm[col0 + 4];
    float4 bt0 = *(const float4*)&bnb[col0], bt1 = *(const float4*)&bnb[col0 + 4];
    float bb[8] = {bp0.x, bp0.y, bp0.z, bp0.w, bp1.x, bp1.y, bp1.z, bp1.w};
    float sc[8], mu[8], be[8];
    {
        float gmv[8] = {gm0.x, gm0.y, gm0.z, gm0.w, gm1.x, gm1.y, gm1.z, gm1.w};
        float vrv[8] = {vr0.x, vr0.y, vr0.z, vr0.w, vr1.x, vr1.y, vr1.z, vr1.w};
        float mnv[8] = {mn0.x, mn0.y, mn0.z, mn0.w, mn1.x, mn1.y, mn1.z, mn1.w};
        float btv[8] = {bt0.x, bt0.y, bt0.z, bt0.w, bt1.x, bt1.y, bt1.z, bt1.w};
        #pragma unroll
        for (int j = 0; j < 8; j++) {
            sc[j] = gmv[j] * rsqrtf(vrv[j] + 1e-5f);
            mu[j] = mnv[j]; be[j] = btv[j];
        }
    }
    #pragma unroll
    for (int i = 0; i < 4; i++) {
        float v[8];
        #pragma unroll
        for (int j = 0; j < 8; j++)
            v[j] = (elu1(acc[i][j] + bb[j]) - mu[j]) * sc[j] + be[j];
        const size_t row = (size_t)bm * 64 + tm * 4 + i;
        *(float4*)&out[row * 128 + col0]     = make_float4(v[0], v[1], v[2], v[3]);
        *(float4*)&out[row * 128 + col0 + 4] = make_float4(v[4], v[5], v[6], v[7]);
    }
}

} // namespace

extern "C" void kernel_launch(void* const* d_in, const int* in_sizes, int n_in,
                              void* d_out, int out_size) {
    const float* rep_pt = (const float*)d_in[0];
    const float* pts    = (const float*)d_in[1];
    const float* fts    = (const float*)d_in[2];
    const float* w1     = (const float*)d_in[3];
    const float* b1     = (const float*)d_in[4];
    const float* w2     = (const float*)d_in[5];
    const float* b2     = (const float*)d_in[6];
    const float* wc1    = (const float*)d_in[7];
    const float* bc1    = (const float*)d_in[8];
    const float* wx1    = (const float*)d_in[9];
    const float* bx1    = (const float*)d_in[10];
    const float* wx2    = (const float*)d_in[11];
    const float* bx2    = (const float*)d_in[12];
    const float* wdw    = (const float*)d_in[13];
    const float* bdw    = (const float*)d_in[14];
    const float* wpw    = (const float*)d_in[15];
    const float* bpw    = (const float*)d_in[16];
    const float* bng    = (const float*)d_in[17];
    const float* bnb    = (const float*)d_in[18];
    const float* bnm    = (const float*)d_in[19];
    const float* bnv    = (const float*)d_in[20];
    float* out = (float*)d_out;

    static bool attr_done = false;
    if (!attr_done) {
        cudaFuncSetAttribute(kernelA, cudaFuncAttributeMaxDynamicSharedMemorySize,
                             A_SMEM * (int)sizeof(float));
        cudaFuncSetAttribute(kernelD, cudaFuncAttributeMaxDynamicSharedMemorySize,
                             D_SMEM * (int)sizeof(float));
        attr_done = true;
    }

    float* pX0; cudaGetSymbolAddress((void**)&pX0, g_X0);
    float* pX1; cudaGetSymbolAddress((void**)&pX1, g_X1);
    float* pXf; cudaGetSymbolAddress((void**)&pXf, g_Xf);

    kernelA<<<NPTS / 16, A_T, A_SMEM * sizeof(float)>>>(
        rep_pt, pts, w1, b1, w2, b2, wc1, bc1);
    gemm256<1><<<256, 256>>>(pX0, wx1, bx1, pX1);
    gemm256<0><<<256, 256>>>(pX1, wx2, bx2, pXf);
    kernelD<<<NPTS / 16, D_T, D_SMEM * sizeof(float)>>>(fts, wdw, bdw);
    gemm_out<<<NPTS / 64, 256>>>(wpw, bpw, bng, bnb, bnm, bnv, out);
}